// round 16
// baseline (speedup 1.0000x reference)
#include <cstdint>
#include <stdint.h>
#include <cuda_runtime.h>
#include <cuda_bf16.h>
#include <math.h>

using std::uint32_t;
using std::uint64_t;

#define N_NODES 50000
#define N_EDGES 800000
#define DIM 128
#define NUM_HEADS 8
#define HEAD_DIM 16

// HMMA GEMM tiling (both edge-E and QKV paths)
#define EBM 128            // rows per block
#define KCHUNK 64          // k per SMEM chunk
#define NCHUNK 2
#define ASTRIDE 72         // halves per row in SMEM tiles (36 words: ldsm conflict-free)
#define ESTRIDE 132        // floats per row of E spill tile

#define TILE_BYTES (EBM * ASTRIDE * 2)          // 18,432
#define GEMM_DYN_SMEM (4 * TILE_BYTES)          // 73,728

// Scratch (static device globals -- allocation-free per harness rules)
__device__ float gQ[N_NODES * DIM];
__device__ float gK[N_NODES * DIM];
__device__ float gV[N_NODES * DIM];
__device__ float gZ[N_NODES * NUM_HEADS];
// W^T hi/lo bf16 splits, [n][k]; index 0=We, 1=Wq, 2=Wk, 3=Wv
__device__ __nv_bfloat16 gWTh[4][DIM * DIM];
__device__ __nv_bfloat16 gWTl[4][DIM * DIM];

// ---------------------------------------------------------------------------
// helpers
// ---------------------------------------------------------------------------
__device__ __forceinline__ uint32_t smem_u32(const void* p) {
    uint32_t a;
    asm("{ .reg .u64 t; cvta.to.shared.u64 t, %1; cvt.u32.u64 %0, t; }"
        : "=r"(a) : "l"(p));
    return a;
}

__device__ __forceinline__ void red_add_v4(float* addr, float4 v) {
    asm volatile("red.global.add.v4.f32 [%0], {%1,%2,%3,%4};"
                 :: "l"(addr), "f"(v.x), "f"(v.y), "f"(v.z), "f"(v.w)
                 : "memory");
}

__device__ __forceinline__ void ldsm_x4(uint32_t (&r)[4], uint32_t addr) {
    asm volatile("ldmatrix.sync.aligned.m8n8.x4.shared.b16 {%0,%1,%2,%3}, [%4];"
                 : "=r"(r[0]), "=r"(r[1]), "=r"(r[2]), "=r"(r[3]) : "r"(addr));
}

// m16n8k16 bf16 HMMA, fp32 accumulate (base sm_80+ PTX)
__device__ __forceinline__ void mma16816(float (&d)[4],
                                         const uint32_t* a,
                                         uint32_t b0, uint32_t b1) {
    asm volatile(
        "mma.sync.aligned.m16n8k16.row.col.f32.bf16.bf16.f32 "
        "{%0,%1,%2,%3}, {%4,%5,%6,%7}, {%8,%9}, {%0,%1,%2,%3};"
        : "+f"(d[0]), "+f"(d[1]), "+f"(d[2]), "+f"(d[3])
        : "r"(a[0]), "r"(a[1]), "r"(a[2]), "r"(a[3]), "r"(b0), "r"(b1));
}

// ---------------------------------------------------------------------------
// Prep: split all four W^T into hi/lo bf16 (tiny, once per launch)
// ---------------------------------------------------------------------------
__global__ void prep_kernel(const float* __restrict__ We,
                            const float* __restrict__ Wq,
                            const float* __restrict__ Wk,
                            const float* __restrict__ Wv) {
    int i = blockIdx.x * blockDim.x + threadIdx.x;
    if (i >= 4 * DIM * DIM) return;
    int iw = i >> 14;
    int rem = i & 16383;
    int n = rem >> 7, k = rem & 127;
    const float* W = (iw == 0) ? We : (iw == 1) ? Wq : (iw == 2) ? Wk : Wv;
    float w = W[k * DIM + n];
    __nv_bfloat16 h = __float2bfloat16_rn(w);
    float lo = w - __bfloat162float(h);
    gWTh[iw][n * DIM + k] = h;
    gWTl[iw][n * DIM + k] = __float2bfloat16_rn(lo);
}

// ---------------------------------------------------------------------------
// Zero init: d_out (wV accumulator) and gZ
// ---------------------------------------------------------------------------
__global__ void zero_kernel(float* __restrict__ out) {
    int i = blockIdx.x * blockDim.x + threadIdx.x;
    if (i < N_NODES * DIM) out[i] = 0.f;
    if (i < N_NODES * NUM_HEADS) gZ[i] = 0.f;
}

// ---------------------------------------------------------------------------
// Shared GEMM building blocks (128 rows x 128 cols, bf16x3 split precision)
// Warp grid 4x2: warp (wm = warp&3, wn = warp>>2) owns rows [wm*32,+32) x
// cols [wn*64,+64).  acc[mt 2][nt 8][4].
// ---------------------------------------------------------------------------
__device__ __forceinline__ void fill_A_chunk(
    const float* __restrict__ A, int row0, bool guard, int c,
    uint32_t sAh, uint32_t sAl, int tid)
{
    for (int i = tid; i < EBM * (KCHUNK / 4); i += 256) {
        int row = i >> 4, q = i & 15;
        int grow = row0 + row;
        float4 v = make_float4(0.f, 0.f, 0.f, 0.f);
        if (!guard || grow < N_NODES)
            v = *(const float4*)(A + (size_t)grow * DIM + c * KCHUNK + q * 4);
        __nv_bfloat162 h01 = __float22bfloat162_rn(make_float2(v.x, v.y));
        __nv_bfloat162 h23 = __float22bfloat162_rn(make_float2(v.z, v.w));
        float2 r01 = make_float2(v.x - __bfloat162float(__low2bfloat16(h01)),
                                 v.y - __bfloat162float(__high2bfloat16(h01)));
        float2 r23 = make_float2(v.z - __bfloat162float(__low2bfloat16(h23)),
                                 v.w - __bfloat162float(__high2bfloat16(h23)));
        __nv_bfloat162 l01 = __float22bfloat162_rn(r01);
        __nv_bfloat162 l23 = __float22bfloat162_rn(r23);
        uint32_t hp0 = *(uint32_t*)&h01, hp1 = *(uint32_t*)&h23;
        uint32_t lp0 = *(uint32_t*)&l01, lp1 = *(uint32_t*)&l23;
        uint32_t off = (uint32_t)(row * ASTRIDE + q * 4) * 2;   // bytes
        asm volatile("st.shared.v2.b32 [%0], {%1,%2};"
                     :: "r"(sAh + off), "r"(hp0), "r"(hp1) : "memory");
        asm volatile("st.shared.v2.b32 [%0], {%1,%2};"
                     :: "r"(sAl + off), "r"(lp0), "r"(lp1) : "memory");
    }
}

__device__ __forceinline__ void fill_B_chunk(
    const __nv_bfloat16* __restrict__ Wh, const __nv_bfloat16* __restrict__ Wl,
    int c, uint32_t sBh, uint32_t sBl, int tid)
{
    for (int i = tid; i < DIM * 8; i += 256) {
        int row = i >> 3, q = i & 7;
        uint4 hv = *(const uint4*)(Wh + row * DIM + c * KCHUNK + q * 8);
        uint4 lv = *(const uint4*)(Wl + row * DIM + c * KCHUNK + q * 8);
        uint32_t off = (uint32_t)(row * ASTRIDE + q * 8) * 2;   // bytes
        asm volatile("st.shared.v4.b32 [%0], {%1,%2,%3,%4};"
                     :: "r"(sBh + off), "r"(hv.x), "r"(hv.y), "r"(hv.z), "r"(hv.w)
                     : "memory");
        asm volatile("st.shared.v4.b32 [%0], {%1,%2,%3,%4};"
                     :: "r"(sBl + off), "r"(lv.x), "r"(lv.y), "r"(lv.z), "r"(lv.w)
                     : "memory");
    }
}

// MMA mainloop over one k-chunk; warp-tiled 32x64; ldmatrix fragment loads.
__device__ __forceinline__ void mma_chunk(
    float (&acc)[2][8][4],
    uint32_t sAh, uint32_t sAl, uint32_t sBh, uint32_t sBl,
    int warp, int lane)
{
    const int wm = warp & 3;
    const int wn = warp >> 2;
    const int t8 = lane & 7;
    const int sel = lane >> 3;

#pragma unroll
    for (int ks = 0; ks < 4; ks++) {
        uint32_t ah[2][4], al[2][4];
#pragma unroll
        for (int mt = 0; mt < 2; mt++) {
            uint32_t arow = (uint32_t)(wm * 32 + mt * 16 + t8 + (sel & 1) * 8);
            uint32_t acol = (uint32_t)(ks * 16 + (sel >> 1) * 8);
            uint32_t aoff = (arow * ASTRIDE + acol) * 2;
            ldsm_x4(ah[mt], sAh + aoff);
            ldsm_x4(al[mt], sAl + aoff);
        }
#pragma unroll
        for (int nb = 0; nb < 4; nb++) {
            uint32_t brow = (uint32_t)(wn * 64 + nb * 16 + t8 + (sel >> 1) * 8);
            uint32_t bcol = (uint32_t)(ks * 16 + (sel & 1) * 8);
            uint32_t boff = (brow * ASTRIDE + bcol) * 2;
            uint32_t bh[4], bl[4];
            ldsm_x4(bh, sBh + boff);
            ldsm_x4(bl, sBl + boff);
#pragma unroll
            for (int mt = 0; mt < 2; mt++) {
#pragma unroll
                for (int nn = 0; nn < 2; nn++) {
                    float (&d)[4] = acc[mt][nb * 2 + nn];
                    mma16816(d, ah[mt], bh[nn * 2], bh[nn * 2 + 1]);  // Ah*Bh
                    mma16816(d, ah[mt], bl[nn * 2], bl[nn * 2 + 1]);  // Ah*Bl
                    mma16816(d, al[mt], bh[nn * 2], bh[nn * 2 + 1]);  // Al*Bh
                }
            }
        }
    }
}

// ---------------------------------------------------------------------------
// QKV projections on the HMMA path: grid (ceil(N/128), 1, 3)
// ---------------------------------------------------------------------------
__global__ __launch_bounds__(256, 2)
void qkv_kernel(const float* __restrict__ x,
                const float* __restrict__ bq,
                const float* __restrict__ bk,
                const float* __restrict__ bv)
{
    extern __shared__ char dyn_smem[];
    const int tid = threadIdx.x;
    const int warp = tid >> 5;
    const int lane = tid & 31;
    const int row0 = blockIdx.x * EBM;
    const int z = blockIdx.z;

    const __nv_bfloat16* Wh = gWTh[z + 1];
    const __nv_bfloat16* Wl = gWTl[z + 1];
    const float* bias = (z == 0) ? bq : (z == 1) ? bk : bv;
    float* out = (z == 0) ? gQ : (z == 1) ? gK : gV;

    const uint32_t base = smem_u32(dyn_smem);
    const uint32_t sAh = base;
    const uint32_t sAl = base + TILE_BYTES;
    const uint32_t sBh = base + 2 * TILE_BYTES;
    const uint32_t sBl = base + 3 * TILE_BYTES;

    float acc[2][8][4];
#pragma unroll
    for (int mt = 0; mt < 2; mt++)
#pragma unroll
        for (int nt = 0; nt < 8; nt++)
#pragma unroll
            for (int j = 0; j < 4; j++) acc[mt][nt][j] = 0.f;

    for (int c = 0; c < NCHUNK; c++) {
        if (c > 0) __syncthreads();
        fill_A_chunk(x, row0, true, c, sAh, sAl, tid);
        fill_B_chunk(Wh, Wl, c, sBh, sBl, tid);
        __syncthreads();
        mma_chunk(acc, sAh, sAl, sBh, sBl, warp, lane);
    }

    // store with bias
    const int wm = warp & 3, wn = warp >> 2;
    const int g = lane >> 2, cc = lane & 3;
#pragma unroll
    for (int mt = 0; mt < 2; mt++) {
#pragma unroll
        for (int nt = 0; nt < 8; nt++) {
            int col = wn * 64 + nt * 8 + cc * 2;
            float b0 = bias[col], b1 = bias[col + 1];
            int r0 = row0 + wm * 32 + mt * 16 + g;
            if (r0 < N_NODES)
                *(float2*)(out + (size_t)r0 * DIM + col) =
                    make_float2(acc[mt][nt][0] + b0, acc[mt][nt][1] + b1);
            if (r0 + 8 < N_NODES)
                *(float2*)(out + (size_t)(r0 + 8) * DIM + col) =
                    make_float2(acc[mt][nt][2] + b0, acc[mt][nt][3] + b1);
        }
    }
}

// ---------------------------------------------------------------------------
// Fused edge kernel: HMMA E-GEMM + warp-per-edge score phase + atomics
// ---------------------------------------------------------------------------
__global__ __launch_bounds__(256, 2)
void edge_kernel(const float* __restrict__ ea,
                 const int* __restrict__ eidx,
                 const float* __restrict__ be,
                 float* __restrict__ wV)
{
    extern __shared__ char dyn_smem[];
    __shared__ int src_s[EBM], dst_s[EBM];
    __shared__ float score_s[EBM][NUM_HEADS];

    const int tid = threadIdx.x;
    const int warp = tid >> 5;
    const int lane = tid & 31;
    const int e0 = blockIdx.x * EBM;

    const uint32_t base = smem_u32(dyn_smem);
    const uint32_t sAh = base;
    const uint32_t sAl = base + TILE_BYTES;
    const uint32_t sBh = base + 2 * TILE_BYTES;
    const uint32_t sBl = base + 3 * TILE_BYTES;

    if (tid < EBM) {
        src_s[tid] = eidx[e0 + tid];
        dst_s[tid] = eidx[N_EDGES + e0 + tid];
    }

    float acc[2][8][4];
#pragma unroll
    for (int mt = 0; mt < 2; mt++)
#pragma unroll
        for (int nt = 0; nt < 8; nt++)
#pragma unroll
            for (int j = 0; j < 4; j++) acc[mt][nt][j] = 0.f;

    for (int c = 0; c < NCHUNK; c++) {
        if (c > 0) __syncthreads();
        fill_A_chunk(ea, e0, false, c, sAh, sAl, tid);
        fill_B_chunk(gWTh[0], gWTl[0], c, sBh, sBl, tid);
        __syncthreads();
        mma_chunk(acc, sAh, sAl, sBh, sBl, warp, lane);
    }

    __syncthreads();   // all warps done reading tiles before Es overwrite

    // --- spill E (+ bias be folded in) to SMEM: Es[128][132] floats ---
    {
        float* Es = (float*)dyn_smem;
        const int wm = warp & 3, wn = warp >> 2;
        const int g = lane >> 2, cc = lane & 3;
#pragma unroll
        for (int mt = 0; mt < 2; mt++) {
#pragma unroll
            for (int nt = 0; nt < 8; nt++) {
                int row = wm * 32 + mt * 16 + g;
                int col = wn * 64 + nt * 8 + cc * 2;
                float2 bb = *(const float2*)(be + col);
                *(float2*)&Es[row * ESTRIDE + col] =
                    make_float2(acc[mt][nt][0] + bb.x, acc[mt][nt][1] + bb.y);
                *(float2*)&Es[(row + 8) * ESTRIDE + col] =
                    make_float2(acc[mt][nt][2] + bb.x, acc[mt][nt][3] + bb.y);
            }
        }
    }
    __syncthreads();

    // --- warp-per-edge scores: warp w handles edges [w*16, w*16+16) ---
    // Each lane loads 4 contiguous cols of K[src], Q[dst] (coalesced LDG.128)
    // and E (LDS.128); head h = lane>>2 reduced over its 4 lanes by shfl.
    {
        const float* Es = (const float*)dyn_smem;
        const int m0 = warp * 16;
#pragma unroll 4
        for (int mi = 0; mi < 16; mi++) {
            const int m = m0 + mi;
            const int srcn = src_s[m];
            const int dstn = dst_s[m];
            float4 kv = *(const float4*)(gK + (size_t)srcn * DIM + lane * 4);
            float4 qv = *(const float4*)(gQ + (size_t)dstn * DIM + lane * 4);
            float4 ev = *(const float4*)(Es + m * ESTRIDE + lane * 4);
            float p = kv.x * qv.x * ev.x + kv.y * qv.y * ev.y
                    + kv.z * qv.z * ev.z + kv.w * qv.w * ev.w;
            p += __shfl_xor_sync(0xffffffffu, p, 1);
            p += __shfl_xor_sync(0xffffffffu, p, 2);
            if ((lane & 3) == 0) {
                float s = p * 0.25f;   // 1/sqrt(HEAD_DIM=16)
                s = fminf(fmaxf(s, -5.f), 5.f);
                score_s[m][lane >> 2] = expf(s);
            }
        }
    }
    __syncthreads();

    // Z reductions: 128 edges x 2 float4 = 256 ops
    {
        int mm = tid >> 1;
        int hh4 = (tid & 1) * 4;
        float4 sv = *(float4*)&score_s[mm][hh4];
        red_add_v4(&gZ[(size_t)dst_s[mm] * NUM_HEADS + hh4], sv);
    }

    // messages: warp per edge, 32 lanes x float4 of V, scaled per-head
#pragma unroll
    for (int it = tid; it < EBM * 32; it += 256) {
        int mm = it >> 5;
        int c4 = it & 31;
        float4 vv = *(const float4*)(gV + (size_t)src_s[mm] * DIM + c4 * 4);
        float sc = score_s[mm][c4 >> 2];
        vv.x *= sc; vv.y *= sc; vv.z *= sc; vv.w *= sc;
        red_add_v4(wV + (size_t)dst_s[mm] * DIM + c4 * 4, vv);
    }
}

// ---------------------------------------------------------------------------
// Finalize: out = wV / (Z + 1e-6)
// ---------------------------------------------------------------------------
__global__ void finalize_kernel(float* __restrict__ out) {
    int i = blockIdx.x * blockDim.x + threadIdx.x;
    if (i >= N_NODES * 32) return;
    int n = i >> 5;
    int c4 = i & 31;
    float* p = out + (size_t)n * DIM + c4 * 4;
    float4 v = *(float4*)p;
    float inv = 1.f / (gZ[n * NUM_HEADS + (c4 >> 2)] + 1e-6f);
    v.x *= inv; v.y *= inv; v.z *= inv; v.w *= inv;
    *(float4*)p = v;
}

// ---------------------------------------------------------------------------
extern "C" void kernel_launch(void* const* d_in, const int* in_sizes, int n_in,
                              void* d_out, int out_size)
{
    const float* x  = (const float*)d_in[0];
    const float* ea = (const float*)d_in[1];
    const int* eidx = (const int*)d_in[2];
    const float* Wq = (const float*)d_in[3];
    const float* bq = (const float*)d_in[4];
    const float* Wk = (const float*)d_in[5];
    const float* bk = (const float*)d_in[6];
    const float* We = (const float*)d_in[7];
    const float* be = (const float*)d_in[8];
    const float* Wv = (const float*)d_in[9];
    const float* bv = (const float*)d_in[10];
    float* out = (float*)d_out;

    cudaFuncSetAttribute(edge_kernel,
                         cudaFuncAttributeMaxDynamicSharedMemorySize, GEMM_DYN_SMEM);
    cudaFuncSetAttribute(qkv_kernel,
                         cudaFuncAttributeMaxDynamicSharedMemorySize, GEMM_DYN_SMEM);

    prep_kernel<<<(4 * DIM * DIM + 255) / 256, 256>>>(We, Wq, Wk, Wv);

    zero_kernel<<<(N_NODES * DIM + 255) / 256, 256>>>(out);

    dim3 gqkv((N_NODES + EBM - 1) / EBM, 1, 3);
    qkv_kernel<<<gqkv, 256, GEMM_DYN_SMEM>>>(x, bq, bk, bv);

    edge_kernel<<<N_EDGES / EBM, 256, GEMM_DYN_SMEM>>>(ea, eidx, be, out);

    finalize_kernel<<<(N_NODES * 32 + 255) / 256, 256>>>(out);
}